// round 12
// baseline (speedup 1.0000x reference)
#include <cuda_runtime.h>
#include <math.h>

#define BB 16
#define NAH 3
#define HH 76
#define WW 76
#define HW (HH*WW)     // 5776 (even)
#define PP (NAH*HW)    // 17328
#define NC 80
#define CH 85
#define TT 20
#define BLK 256
#define NW  (BLK/32)                   // 8
#define PPT 2
#define GX  ((PP/PPT + BLK - 1)/BLK)   // 34 spatial blocks per batch
#define FBX ((TT + NW - 1)/NW)         // 3 fore blocks per batch (1 warp/target)
#define NBLK ((GX + FBX)*BB)           // 592

__constant__ float c_aw[9] = {10.f,16.f,33.f,30.f,62.f,59.f,116.f,156.f,373.f};
__constant__ float c_ah[9] = {13.f,30.f,23.f,61.f,45.f,119.f,90.f,198.f,326.f};

__device__ double   g_acc[3];       // statically zero; returned to zero every run
__device__ unsigned g_ticket = 0;   // wraps to 0 every run via atomicInc

__device__ __forceinline__ float ex2f(float x){ float y; asm("ex2.approx.f32 %0,%1;" : "=f"(y) : "f"(x)); return y; }
__device__ __forceinline__ float lg2f(float x){ float y; asm("lg2.approx.f32 %0,%1;" : "=f"(y) : "f"(x)); return y; }
__device__ __forceinline__ float tanha(float x){ float y; asm("tanh.approx.f32 %0,%1;" : "=f"(y) : "f"(x)); return y; }

#define L2E 1.4426950408889634f
#define LN2 0.6931471805599453f

__device__ __forceinline__ float fexp(float x)     { return ex2f(x * L2E); }
__device__ __forceinline__ float flog(float x)     { return LN2 * lg2f(x); }
__device__ __forceinline__ float fsigmoid(float x) { return fmaf(0.5f, tanha(0.5f*x), 0.5f); }
__device__ __forceinline__ float fsoftplus(float z){ return LN2 * lg2f(1.f + ex2f(z * L2E)); }

// full matching (fore path only)
struct Match {
    bool  valid, ok;
    int   flat, cls;
    float g1x, g1y, g2x, g2y, thr4;      // thr4 = (ga + 1e-9)/4
    float tx, ty, tw, th, sc;
};

__device__ __forceinline__ Match match_slot(const float* __restrict__ tgt, int b, int slot) {
    Match m;
    const float* tr = tgt + (size_t)(b*TT + slot)*5;
    const float wn = tr[2], hn = tr[3];
    const float cx = tr[0]*608.f, cy = tr[1]*608.f;
    const float gw = wn*608.f,    gh = hn*608.f;
    m.valid = (wn > 0.f);
    if (m.valid) {
        m.g1x = cx - 0.5f*gw;  m.g2x = cx + 0.5f*gw;
        m.g1y = cy - 0.5f*gh;  m.g2y = cy + 0.5f*gh;
        m.thr4 = 0.25f*(gw*gh + 1e-9f);
    } else {
        m.g1x = 1e30f; m.g2x = -1e30f;
        m.g1y = 1e30f; m.g2y = -1e30f;
        m.thr4 = 1e30f;
    }
    const float ga = gw*gh;
    float bestI = fminf(gw, c_aw[0]) * fminf(gh, c_ah[0]);
    float bestD = ga + c_aw[0]*c_ah[0] - bestI + 1e-9f;
    int best = 0;
    #pragma unroll
    for (int k = 1; k < 9; k++) {
        const float ik = fminf(gw, c_aw[k]) * fminf(gh, c_ah[k]);
        const float dk = ga + c_aw[k]*c_ah[k] - ik + 1e-9f;
        if (ik*bestD > bestI*dk) { bestI = ik; bestD = dk; best = k; }  // first max wins
    }
    m.ok = m.valid && (best <= 2);
    const float gxs = cx * 0.125f, gys = cy * 0.125f;
    int gi = (int)floorf(gxs); gi = min(max(gi, 0), WW-1);
    int gj = (int)floorf(gys); gj = min(max(gj, 0), HH-1);
    m.flat = m.ok ? (best*HW + gj*WW + gi) : -0x40000000;
    m.tx = gxs - (float)gi;
    m.ty = gys - (float)gj;
    m.tw = flog(fmaxf(gw, 1e-30f) / c_aw[best]);
    m.th = flog(fmaxf(gh, 1e-30f) / c_ah[best]);
    m.sc = 2.f - wn*hn;
    m.cls = (int)tr[4];
    return m;
}

__global__ __launch_bounds__(BLK, 4)
void yolo_k(const float* __restrict__ x, const float* __restrict__ tgt,
            float* __restrict__ out)
{
    __shared__ float4 s_box[NW][TT];
    __shared__ float  s_thr[NW][TT];   // thr4
    __shared__ float  sred[3][NW];

    const int b    = blockIdx.y;
    const int bx   = blockIdx.x;
    const int tid  = threadIdx.x;
    const int wid  = tid >> 5;
    const int lane = tid & 31;

    float accL = 0.f, accC = 0.f, accS = 0.f;

    if (bx < GX) {
        // ========== spatial path: uniform, no fore logic at all ==========
        const int lin  = bx*BLK + tid;
        const int pos2 = lin*PPT;
        const bool act = (pos2 < PP);
        const int a    = act ? (pos2 / HW) : 0;
        const int cell = act ? (pos2 - a*HW) : 0;
        const int j    = cell / WW;
        const int i0   = cell - j*WW;
        const size_t off = ((size_t)(b*NAH + a)*CH)*HW + (size_t)cell;

        float2 RX, RY, RW, RH, RC;
        if (act) {
            RX = *(const float2*)(x + off);
            RY = *(const float2*)(x + off +   (size_t)HW);
            RW = *(const float2*)(x + off + 2*(size_t)HW);
            RH = *(const float2*)(x + off + 3*(size_t)HW);
            RC = *(const float2*)(x + off + 4*(size_t)HW);
        } else {
            RX = RY = RW = RH = RC = make_float2(0.f, 0.f);
        }

        // light prep: spatial warps need only box + thr4 (no argmax, no logs)
        if (lane < TT) {
            const float* tr = tgt + (size_t)(b*TT + lane)*5;
            const float wn = tr[2], hn = tr[3];
            const float cx = tr[0]*608.f, cy = tr[1]*608.f;
            const float gw = wn*608.f,    gh = hn*608.f;
            const bool valid = (wn > 0.f);
            s_box[wid][lane] = valid ? make_float4(cx - 0.5f*gw, cy - 0.5f*gh,
                                                   cx + 0.5f*gw, cy + 0.5f*gh)
                                     : make_float4(1e30f, 1e30f, -1e30f, -1e30f);
            s_thr[wid][lane] = valid ? 0.25f*(gw*gh + 1e-9f) : 1e30f;
        }

        const float rx[2] = {RX.x,RX.y};
        const float ry[2] = {RY.x,RY.y};
        const float rw[2] = {RW.x,RW.y};
        const float rh[2] = {RH.x,RH.y};
        const float rc[2] = {RC.x,RC.y};
        const float awh = 0.5f*c_aw[a], ahh = 0.5f*c_ah[a];

        float d1x[2], d2x[2], d1y[2], d2y[2], da4[2], spc[2];
        #pragma unroll
        for (int s = 0; s < PPT; s++) {
            const float sxv = fsigmoid(rx[s]);
            const float syv = fsigmoid(ry[s]);
            const float hw  = fexp(rw[s]) * awh;       // half-width
            const float hh  = fexp(rh[s]) * ahh;       // half-height
            const float dcx = (sxv + (float)(i0 + s)) * 8.f;
            const float dcy = (syv + (float)j) * 8.f;
            d1x[s] = dcx - hw;  d2x[s] = dcx + hw;
            d1y[s] = dcy - hh;  d2y[s] = dcy + hh;
            da4[s] = hw*hh;                            // da/4
            spc[s] = fsoftplus(rc[s]);                 // background conf term
        }
        __syncwarp();

        float vm[2] = {-1e30f, -1e30f};                // max_t(0.75*inter - thr4)
        #pragma unroll
        for (int t = 0; t < TT; t++) {
            const float4 g    = s_box[wid][t];
            const float  thr4 = s_thr[wid][t];
            #pragma unroll
            for (int s = 0; s < PPT; s++) {
                const float iw = fmaxf(fminf(d2x[s], g.z) - fmaxf(d1x[s], g.x), 0.f);
                const float ih = fmaxf(fminf(d2y[s], g.w) - fmaxf(d1y[s], g.y), 0.f);
                vm[s] = fmaxf(vm[s], fmaf(0.75f, iw*ih, -thr4));
            }
        }
        if (act) {
            #pragma unroll
            for (int s = 0; s < PPT; s++)
                if (!(vm[s] > da4[s])) accC += spc[s];   // bg conf (fore incl.)
        }

        // reduce conf only
        #pragma unroll
        for (int o = 16; o > 0; o >>= 1)
            accC += __shfl_down_sync(0xffffffffu, accC, o);
        if (lane == 0) sred[1][wid] = accC;
        __syncthreads();
        if (tid == 0) {
            double q1 = 0.0;
            #pragma unroll
            for (int k = 0; k < NW; k++) q1 += (double)sred[1][k];
            atomicAdd(&g_acc[1], q1);
        }
    } else {
        // ========== fore path: one warp per (batch, target) ==========
        const int T = (bx - GX)*NW + wid;     // 0..23; guard below
        Match m;
        bool okl = false; int flatl = -0x40000000;
        if (lane < TT) { m = match_slot(tgt, b, lane); okl = m.ok; flatl = m.flat; }

        if (T < TT) {
            const unsigned FULL = 0xffffffffu;
            const int myflat = __shfl_sync(FULL, flatl, T);
            const bool myok  = (__shfl_sync(FULL, (int)okl, T) != 0);
            const unsigned same = __ballot_sync(FULL, okl && (flatl == myflat));
            const bool win = myok && ((same >> (T+1)) == 0);   // last-wins dedup

            if (win) {
                const float tx = __shfl_sync(FULL, m.tx, T);
                const float ty = __shfl_sync(FULL, m.ty, T);
                const float tw = __shfl_sync(FULL, m.tw, T);
                const float th = __shfl_sync(FULL, m.th, T);
                const float w2 = __shfl_sync(FULL, m.sc, T);
                const int   cc = __shfl_sync(FULL, m.cls, T);

                const int fa    = myflat / HW;
                const int fcell = myflat - fa*HW;
                const int fj    = fcell / WW;
                const int fi    = fcell - fj*WW;
                const size_t so = ((size_t)(b*NAH + fa)*CH)*HW + (size_t)fcell;

                const float v5 = (lane < 5) ? x[so + (size_t)lane*HW] : 0.f;
                const float frx = __shfl_sync(FULL, v5, 0);
                const float fry = __shfl_sync(FULL, v5, 1);
                const float frw = __shfl_sync(FULL, v5, 2);
                const float frh = __shfl_sync(FULL, v5, 3);
                const float frc = __shfl_sync(FULL, v5, 4);

                // decode (IDENTICAL formulas to spatial path)
                const float fsx = fsigmoid(frx), fsy = fsigmoid(fry);
                const float fhw = fexp(frw) * (0.5f*c_aw[fa]);
                const float fhh = fexp(frh) * (0.5f*c_ah[fa]);
                const float fdcx = (fsx + (float)fi) * 8.f;
                const float fdcy = (fsy + (float)fj) * 8.f;
                const float fd1x = fdcx - fhw, fd2x = fdcx + fhw;
                const float fd1y = fdcy - fhh, fd2y = fdcy + fhh;
                const float fda4 = fhw*fhh;

                // recompute the EXACT spatial ignore decision for this position
                float v = -1e30f;
                if (lane < TT) {
                    const float iw = fmaxf(fminf(fd2x, m.g2x) - fmaxf(fd1x, m.g1x), 0.f);
                    const float ih = fmaxf(fminf(fd2y, m.g2y) - fmaxf(fd1y, m.g1y), 0.f);
                    v = fmaf(0.75f, iw*ih, -m.thr4);
                }
                #pragma unroll
                for (int o = 16; o > 0; o >>= 1)
                    v = fmaxf(v, __shfl_xor_sync(FULL, v, o));
                const bool ign = (v > fda4);

                if (lane == 0) {
                    const float d0 = fsx - tx, d1 = fsy - ty;
                    const float d2 = frw - tw, d3 = frh - th;
                    accL += 0.5f*w2*(d0*d0 + d1*d1) + 0.5f*w2*(d2*d2 + d3*d3);
                    // fore conf, minus the bg term the spatial pass overcounted
                    accC += fsoftplus(-frc) - (ign ? 0.f : fsoftplus(frc));
                }
                // cooperative cls: sum_c softplus(rv) - rv_cc
                #pragma unroll
                for (int k = 0; k < 3; k++) {
                    const int c = lane + 32*k;
                    if (c < NC) {
                        const float rv = x[so + (size_t)(5+c)*HW];
                        accS += fsoftplus(rv);
                        if (c == cc) accS -= rv;
                    }
                }
            }
        }

        #pragma unroll
        for (int o = 16; o > 0; o >>= 1) {
            accL += __shfl_down_sync(0xffffffffu, accL, o);
            accC += __shfl_down_sync(0xffffffffu, accC, o);
            accS += __shfl_down_sync(0xffffffffu, accS, o);
        }
        if (lane == 0) { sred[0][wid] = accL; sred[1][wid] = accC; sred[2][wid] = accS; }
        __syncthreads();
        if (tid == 0) {
            double q0 = 0.0, q1 = 0.0, q2 = 0.0;
            #pragma unroll
            for (int k = 0; k < NW; k++) {
                q0 += (double)sred[0][k]; q1 += (double)sred[1][k]; q2 += (double)sred[2][k];
            }
            atomicAdd(&g_acc[0], q0);
            atomicAdd(&g_acc[1], q1);
            atomicAdd(&g_acc[2], q2);
        }
    }

    // ---- common finalize: ticket wraps to 0 each run ----
    if (tid == 0) {
        __threadfence();
        const unsigned old = atomicInc(&g_ticket, NBLK - 1);
        if (old == NBLK - 1) {
            #pragma unroll
            for (int k = 0; k < 3; k++) {
                unsigned long long raw = atomicExch((unsigned long long*)&g_acc[k], 0ull);
                out[k] = (float)(__longlong_as_double(raw) / (double)BB);
            }
        }
    }
}

extern "C" void kernel_launch(void* const* d_in, const int* in_sizes, int n_in,
                              void* d_out, int out_size) {
    const float* x = (const float*)d_in[0];
    const float* t = (const float*)d_in[1];
    float* out = (float*)d_out;
    dim3 grid(GX + FBX, BB);
    yolo_k<<<grid, BLK>>>(x, t, out);
}

// round 13
// speedup vs baseline: 1.0724x; 1.0724x over previous
#include <cuda_runtime.h>
#include <math.h>

#define BB 16
#define NAH 3
#define HH 76
#define WW 76
#define HW (HH*WW)     // 5776 (even)
#define PP (NAH*HW)    // 17328
#define NC 80
#define CH 85
#define TT 20
#define BLK 128
#define NW  (BLK/32)                   // 4
#define PPT 2
#define GX  ((PP/PPT + BLK - 1)/BLK)   // 68 spatial blocks per batch
#define FBX ((TT + NW - 1)/NW)         // 5 fore blocks per batch (1 warp/target)
#define NBLK ((GX + FBX)*BB)           // 1168

__constant__ float c_aw[9] = {10.f,16.f,33.f,30.f,62.f,59.f,116.f,156.f,373.f};
__constant__ float c_ah[9] = {13.f,30.f,23.f,61.f,45.f,119.f,90.f,198.f,326.f};

__device__ double   g_acc[3];       // statically zero; returned to zero every run
__device__ unsigned g_ticket = 0;   // wraps to 0 every run via atomicInc

__device__ __forceinline__ float ex2f(float x){ float y; asm("ex2.approx.f32 %0,%1;" : "=f"(y) : "f"(x)); return y; }
__device__ __forceinline__ float lg2f(float x){ float y; asm("lg2.approx.f32 %0,%1;" : "=f"(y) : "f"(x)); return y; }
__device__ __forceinline__ float tanha(float x){ float y; asm("tanh.approx.f32 %0,%1;" : "=f"(y) : "f"(x)); return y; }

#define L2E 1.4426950408889634f
#define LN2 0.6931471805599453f

__device__ __forceinline__ float fexp(float x)     { return ex2f(x * L2E); }
__device__ __forceinline__ float flog(float x)     { return LN2 * lg2f(x); }
__device__ __forceinline__ float fsigmoid(float x) { return fmaf(0.5f, tanha(0.5f*x), 0.5f); }
__device__ __forceinline__ float fsoftplus(float z){ return LN2 * lg2f(1.f + ex2f(z * L2E)); }

// full matching (fore path only)
struct Match {
    bool  valid, ok;
    int   flat, cls;
    float g1x, g1y, g2x, g2y, thr4;      // thr4 = (ga + 1e-9)/4
    float tx, ty, tw, th, sc;
};

__device__ __forceinline__ Match match_slot(const float* __restrict__ tgt, int b, int slot) {
    Match m;
    const float* tr = tgt + (size_t)(b*TT + slot)*5;
    const float wn = tr[2], hn = tr[3];
    const float cx = tr[0]*608.f, cy = tr[1]*608.f;
    const float gw = wn*608.f,    gh = hn*608.f;
    m.valid = (wn > 0.f);
    if (m.valid) {
        m.g1x = cx - 0.5f*gw;  m.g2x = cx + 0.5f*gw;
        m.g1y = cy - 0.5f*gh;  m.g2y = cy + 0.5f*gh;
        m.thr4 = 0.25f*(gw*gh + 1e-9f);
    } else {
        m.g1x = 1e30f; m.g2x = -1e30f;
        m.g1y = 1e30f; m.g2y = -1e30f;
        m.thr4 = 1e30f;
    }
    const float ga = gw*gh;
    float bestI = fminf(gw, c_aw[0]) * fminf(gh, c_ah[0]);
    float bestD = ga + c_aw[0]*c_ah[0] - bestI + 1e-9f;
    int best = 0;
    #pragma unroll
    for (int k = 1; k < 9; k++) {
        const float ik = fminf(gw, c_aw[k]) * fminf(gh, c_ah[k]);
        const float dk = ga + c_aw[k]*c_ah[k] - ik + 1e-9f;
        if (ik*bestD > bestI*dk) { bestI = ik; bestD = dk; best = k; }  // first max wins
    }
    m.ok = m.valid && (best <= 2);
    const float gxs = cx * 0.125f, gys = cy * 0.125f;
    int gi = (int)floorf(gxs); gi = min(max(gi, 0), WW-1);
    int gj = (int)floorf(gys); gj = min(max(gj, 0), HH-1);
    m.flat = m.ok ? (best*HW + gj*WW + gi) : -0x40000000;
    m.tx = gxs - (float)gi;
    m.ty = gys - (float)gj;
    m.tw = flog(fmaxf(gw, 1e-30f) / c_aw[best]);
    m.th = flog(fmaxf(gh, 1e-30f) / c_ah[best]);
    m.sc = 2.f - wn*hn;
    m.cls = (int)tr[4];
    return m;
}

__global__ __launch_bounds__(BLK, 8)
void yolo_k(const float* __restrict__ x, const float* __restrict__ tgt,
            float* __restrict__ out)
{
    __shared__ float4 s_box[NW][TT];
    __shared__ float  s_thr[NW][TT];   // thr4
    __shared__ float  sred[3][NW];

    const int b    = blockIdx.y;
    const int bx   = blockIdx.x;
    const int tid  = threadIdx.x;
    const int wid  = tid >> 5;
    const int lane = tid & 31;

    float accL = 0.f, accC = 0.f, accS = 0.f;

    if (bx < GX) {
        // ========== spatial path: uniform, no fore logic at all ==========
        const int lin  = bx*BLK + tid;
        const int pos2 = lin*PPT;
        const bool act = (pos2 < PP);
        const int a    = act ? (pos2 / HW) : 0;
        const int cell = act ? (pos2 - a*HW) : 0;
        const int j    = cell / WW;
        const int i0   = cell - j*WW;
        const size_t off = ((size_t)(b*NAH + a)*CH)*HW + (size_t)cell;

        float2 RX, RY, RW, RH, RC;
        if (act) {
            RX = *(const float2*)(x + off);
            RY = *(const float2*)(x + off +   (size_t)HW);
            RW = *(const float2*)(x + off + 2*(size_t)HW);
            RH = *(const float2*)(x + off + 3*(size_t)HW);
            RC = *(const float2*)(x + off + 4*(size_t)HW);
        } else {
            RX = RY = RW = RH = RC = make_float2(0.f, 0.f);
        }

        // warp-parallel valid compaction (ballot + popc rank; order preserved)
        bool   tvalid = false;
        float4 tbox;
        float  tthr = 0.f;
        if (lane < TT) {
            const float* tr = tgt + (size_t)(b*TT + lane)*5;
            const float wn = tr[2], hn = tr[3];
            const float cx = tr[0]*608.f, cy = tr[1]*608.f;
            const float gw = wn*608.f,    gh = hn*608.f;
            tvalid = (wn > 0.f);
            tbox = make_float4(cx - 0.5f*gw, cy - 0.5f*gh,
                               cx + 0.5f*gw, cy + 0.5f*gh);
            tthr = 0.25f*(gw*gh + 1e-9f);
        }
        const unsigned vmask = __ballot_sync(0xffffffffu, tvalid);
        if (tvalid) {
            const int rank = __popc(vmask & ((1u << lane) - 1u));
            s_box[wid][rank] = tbox;
            s_thr[wid][rank] = tthr;
        }
        const int nv = __popc(vmask);

        const float rx[2] = {RX.x,RX.y};
        const float ry[2] = {RY.x,RY.y};
        const float rw[2] = {RW.x,RW.y};
        const float rh[2] = {RH.x,RH.y};
        const float rc[2] = {RC.x,RC.y};
        const float awh = 0.5f*c_aw[a], ahh = 0.5f*c_ah[a];

        float d1x[2], d2x[2], d1y[2], d2y[2], da4[2], spc[2];
        #pragma unroll
        for (int s = 0; s < PPT; s++) {
            const float sxv = fsigmoid(rx[s]);
            const float syv = fsigmoid(ry[s]);
            const float hw  = fexp(rw[s]) * awh;       // half-width
            const float hh  = fexp(rh[s]) * ahh;       // half-height
            const float dcx = (sxv + (float)(i0 + s)) * 8.f;
            const float dcy = (syv + (float)j) * 8.f;
            d1x[s] = dcx - hw;  d2x[s] = dcx + hw;
            d1y[s] = dcy - hh;  d2y[s] = dcy + hh;
            da4[s] = hw*hh;                            // da/4
            spc[s] = fsoftplus(rc[s]);                 // background conf term
        }
        __syncwarp();

        float vm[2] = {-1e30f, -1e30f};                // max_t(0.75*inter - thr4)
        #pragma unroll 5
        for (int t = 0; t < nv; t++) {
            const float4 g    = s_box[wid][t];
            const float  thr4 = s_thr[wid][t];
            #pragma unroll
            for (int s = 0; s < PPT; s++) {
                const float iw = fmaxf(fminf(d2x[s], g.z) - fmaxf(d1x[s], g.x), 0.f);
                const float ih = fmaxf(fminf(d2y[s], g.w) - fmaxf(d1y[s], g.y), 0.f);
                vm[s] = fmaxf(vm[s], fmaf(0.75f, iw*ih, -thr4));
            }
        }
        if (act) {
            #pragma unroll
            for (int s = 0; s < PPT; s++)
                if (!(vm[s] > da4[s])) accC += spc[s];   // bg conf (fore incl.)
        }

        // reduce conf only
        #pragma unroll
        for (int o = 16; o > 0; o >>= 1)
            accC += __shfl_down_sync(0xffffffffu, accC, o);
        if (lane == 0) sred[1][wid] = accC;
        __syncthreads();
        if (tid == 0) {
            double q1 = 0.0;
            #pragma unroll
            for (int k = 0; k < NW; k++) q1 += (double)sred[1][k];
            atomicAdd(&g_acc[1], q1);
        }
    } else {
        // ========== fore path: one warp per (batch, target) ==========
        const int T = (bx - GX)*NW + wid;     // 0..19
        Match m;
        bool okl = false; int flatl = -0x40000000;
        if (lane < TT) { m = match_slot(tgt, b, lane); okl = m.ok; flatl = m.flat; }

        if (T < TT) {
            const unsigned FULL = 0xffffffffu;
            const int myflat = __shfl_sync(FULL, flatl, T);
            const bool myok  = (__shfl_sync(FULL, (int)okl, T) != 0);
            const unsigned same = __ballot_sync(FULL, okl && (flatl == myflat));
            const bool win = myok && ((same >> (T+1)) == 0);   // last-wins dedup

            if (win) {
                const float tx = __shfl_sync(FULL, m.tx, T);
                const float ty = __shfl_sync(FULL, m.ty, T);
                const float tw = __shfl_sync(FULL, m.tw, T);
                const float th = __shfl_sync(FULL, m.th, T);
                const float w2 = __shfl_sync(FULL, m.sc, T);
                const int   cc = __shfl_sync(FULL, m.cls, T);

                const int fa    = myflat / HW;
                const int fcell = myflat - fa*HW;
                const int fj    = fcell / WW;
                const int fi    = fcell - fj*WW;
                const size_t so = ((size_t)(b*NAH + fa)*CH)*HW + (size_t)fcell;

                const float v5 = (lane < 5) ? x[so + (size_t)lane*HW] : 0.f;
                const float frx = __shfl_sync(FULL, v5, 0);
                const float fry = __shfl_sync(FULL, v5, 1);
                const float frw = __shfl_sync(FULL, v5, 2);
                const float frh = __shfl_sync(FULL, v5, 3);
                const float frc = __shfl_sync(FULL, v5, 4);

                // decode (IDENTICAL formulas to spatial path)
                const float fsx = fsigmoid(frx), fsy = fsigmoid(fry);
                const float fhw = fexp(frw) * (0.5f*c_aw[fa]);
                const float fhh = fexp(frh) * (0.5f*c_ah[fa]);
                const float fdcx = (fsx + (float)fi) * 8.f;
                const float fdcy = (fsy + (float)fj) * 8.f;
                const float fd1x = fdcx - fhw, fd2x = fdcx + fhw;
                const float fd1y = fdcy - fhh, fd2y = fdcy + fhh;
                const float fda4 = fhw*fhh;

                // recompute the EXACT spatial ignore decision (invalid slots
                // contribute -1e30, same as being excluded; fp max is
                // order-independent so compaction doesn't change the result)
                float v = -1e30f;
                if (lane < TT) {
                    const float iw = fmaxf(fminf(fd2x, m.g2x) - fmaxf(fd1x, m.g1x), 0.f);
                    const float ih = fmaxf(fminf(fd2y, m.g2y) - fmaxf(fd1y, m.g1y), 0.f);
                    v = fmaf(0.75f, iw*ih, -m.thr4);
                }
                #pragma unroll
                for (int o = 16; o > 0; o >>= 1)
                    v = fmaxf(v, __shfl_xor_sync(FULL, v, o));
                const bool ign = (v > fda4);

                if (lane == 0) {
                    const float d0 = fsx - tx, d1 = fsy - ty;
                    const float d2 = frw - tw, d3 = frh - th;
                    accL += 0.5f*w2*(d0*d0 + d1*d1) + 0.5f*w2*(d2*d2 + d3*d3);
                    // fore conf, minus the bg term the spatial pass overcounted
                    accC += fsoftplus(-frc) - (ign ? 0.f : fsoftplus(frc));
                }
                // cooperative cls: sum_c softplus(rv) - rv_cc
                #pragma unroll
                for (int k = 0; k < 3; k++) {
                    const int c = lane + 32*k;
                    if (c < NC) {
                        const float rv = x[so + (size_t)(5+c)*HW];
                        accS += fsoftplus(rv);
                        if (c == cc) accS -= rv;
                    }
                }
            }
        }

        #pragma unroll
        for (int o = 16; o > 0; o >>= 1) {
            accL += __shfl_down_sync(0xffffffffu, accL, o);
            accC += __shfl_down_sync(0xffffffffu, accC, o);
            accS += __shfl_down_sync(0xffffffffu, accS, o);
        }
        if (lane == 0) { sred[0][wid] = accL; sred[1][wid] = accC; sred[2][wid] = accS; }
        __syncthreads();
        if (tid == 0) {
            double q0 = 0.0, q1 = 0.0, q2 = 0.0;
            #pragma unroll
            for (int k = 0; k < NW; k++) {
                q0 += (double)sred[0][k]; q1 += (double)sred[1][k]; q2 += (double)sred[2][k];
            }
            atomicAdd(&g_acc[0], q0);
            atomicAdd(&g_acc[1], q1);
            atomicAdd(&g_acc[2], q2);
        }
    }

    // ---- common finalize: ticket wraps to 0 each run ----
    if (tid == 0) {
        __threadfence();
        const unsigned old = atomicInc(&g_ticket, NBLK - 1);
        if (old == NBLK - 1) {
            #pragma unroll
            for (int k = 0; k < 3; k++) {
                unsigned long long raw = atomicExch((unsigned long long*)&g_acc[k], 0ull);
                out[k] = (float)(__longlong_as_double(raw) / (double)BB);
            }
        }
    }
}

extern "C" void kernel_launch(void* const* d_in, const int* in_sizes, int n_in,
                              void* d_out, int out_size) {
    const float* x = (const float*)d_in[0];
    const float* t = (const float*)d_in[1];
    float* out = (float*)d_out;
    dim3 grid(GX + FBX, BB);
    yolo_k<<<grid, BLK>>>(x, t, out);
}

// round 14
// speedup vs baseline: 1.2012x; 1.1201x over previous
#include <cuda_runtime.h>
#include <math.h>

#define BB 16
#define NAH 3
#define HH 76
#define WW 76
#define HW (HH*WW)     // 5776 (even)
#define PP (NAH*HW)    // 17328
#define NC 80
#define CH 85
#define TT 20
#define BLK 128
#define NW  (BLK/32)                   // 4
#define PPT 2
#define GX  ((PP/PPT + BLK - 1)/BLK)   // 68 spatial blocks per batch
#define FBX ((TT + NW - 1)/NW)         // 5 fore blocks per batch (1 warp/target)
#define NBLK ((GX + FBX)*BB)           // 1168

__constant__ float c_aw[9] = {10.f,16.f,33.f,30.f,62.f,59.f,116.f,156.f,373.f};
__constant__ float c_ah[9] = {13.f,30.f,23.f,61.f,45.f,119.f,90.f,198.f,326.f};

__device__ double   g_acc[3];       // statically zero; returned to zero every run
__device__ unsigned g_ticket = 0;   // wraps to 0 every run via atomicInc

__device__ __forceinline__ float ex2f(float x){ float y; asm("ex2.approx.f32 %0,%1;" : "=f"(y) : "f"(x)); return y; }
__device__ __forceinline__ float lg2f(float x){ float y; asm("lg2.approx.f32 %0,%1;" : "=f"(y) : "f"(x)); return y; }
__device__ __forceinline__ float tanha(float x){ float y; asm("tanh.approx.f32 %0,%1;" : "=f"(y) : "f"(x)); return y; }

#define L2E 1.4426950408889634f
#define LN2 0.6931471805599453f

__device__ __forceinline__ float fexp(float x)     { return ex2f(x * L2E); }
__device__ __forceinline__ float flog(float x)     { return LN2 * lg2f(x); }
__device__ __forceinline__ float fsigmoid(float x) { return fmaf(0.5f, tanha(0.5f*x), 0.5f); }
__device__ __forceinline__ float fsoftplus(float z){ return LN2 * lg2f(1.f + ex2f(z * L2E)); }

// full matching (fore path only)
struct Match {
    bool  valid, ok;
    int   flat, cls;
    float g1x, g1y, g2x, g2y, thr4;      // thr4 = (ga + 1e-9)/4
    float tx, ty, tw, th, sc;
};

__device__ __forceinline__ Match match_slot(const float* __restrict__ tgt, int b, int slot) {
    Match m;
    const float* tr = tgt + (size_t)(b*TT + slot)*5;
    const float wn = tr[2], hn = tr[3];
    const float cx = tr[0]*608.f, cy = tr[1]*608.f;
    const float gw = wn*608.f,    gh = hn*608.f;
    m.valid = (wn > 0.f);
    if (m.valid) {
        m.g1x = cx - 0.5f*gw;  m.g2x = cx + 0.5f*gw;
        m.g1y = cy - 0.5f*gh;  m.g2y = cy + 0.5f*gh;
        m.thr4 = 0.25f*(gw*gh + 1e-9f);
    } else {
        m.g1x = 1e30f; m.g2x = -1e30f;
        m.g1y = 1e30f; m.g2y = -1e30f;
        m.thr4 = 1e30f;
    }
    const float ga = gw*gh;
    float bestI = fminf(gw, c_aw[0]) * fminf(gh, c_ah[0]);
    float bestD = ga + c_aw[0]*c_ah[0] - bestI + 1e-9f;
    int best = 0;
    #pragma unroll
    for (int k = 1; k < 9; k++) {
        const float ik = fminf(gw, c_aw[k]) * fminf(gh, c_ah[k]);
        const float dk = ga + c_aw[k]*c_ah[k] - ik + 1e-9f;
        if (ik*bestD > bestI*dk) { bestI = ik; bestD = dk; best = k; }  // first max wins
    }
    m.ok = m.valid && (best <= 2);
    const float gxs = cx * 0.125f, gys = cy * 0.125f;
    int gi = (int)floorf(gxs); gi = min(max(gi, 0), WW-1);
    int gj = (int)floorf(gys); gj = min(max(gj, 0), HH-1);
    m.flat = m.ok ? (best*HW + gj*WW + gi) : -0x40000000;
    m.tx = gxs - (float)gi;
    m.ty = gys - (float)gj;
    m.tw = flog(fmaxf(gw, 1e-30f) / c_aw[best]);
    m.th = flog(fmaxf(gh, 1e-30f) / c_ah[best]);
    m.sc = 2.f - wn*hn;
    m.cls = (int)tr[4];
    return m;
}

__global__ __launch_bounds__(BLK, 8)
void yolo_k(const float* __restrict__ x, const float* __restrict__ tgt,
            float* __restrict__ out)
{
    __shared__ float4 s_box[NW][TT];
    __shared__ float  s_thr[NW][TT];   // thr4
    __shared__ float  sred[3][NW];

    const int b    = blockIdx.y;
    const int bx   = blockIdx.x;
    const int tid  = threadIdx.x;
    const int wid  = tid >> 5;
    const int lane = tid & 31;

    float accL = 0.f, accC = 0.f, accS = 0.f;

    if (bx < GX) {
        // ========== spatial path: uniform, no fore logic at all ==========
        const int lin  = bx*BLK + tid;
        const int pos2 = lin*PPT;
        const bool act = (pos2 < PP);
        const int a    = act ? (pos2 / HW) : 0;
        const int cell = act ? (pos2 - a*HW) : 0;
        const int j    = cell / WW;
        const int i0   = cell - j*WW;
        const size_t off = ((size_t)(b*NAH + a)*CH)*HW + (size_t)cell;

        float2 RX, RY, RW, RH, RC;
        if (act) {
            RX = *(const float2*)(x + off);
            RY = *(const float2*)(x + off +   (size_t)HW);
            RW = *(const float2*)(x + off + 2*(size_t)HW);
            RH = *(const float2*)(x + off + 3*(size_t)HW);
            RC = *(const float2*)(x + off + 4*(size_t)HW);
        } else {
            RX = RY = RW = RH = RC = make_float2(0.f, 0.f);
        }

        // warp-parallel valid compaction (ballot + popc rank; order preserved).
        // Tail slots nv..TT-1 get inert sentinels (disjoint addresses -> no race).
        bool   tvalid = false;
        float4 tbox;
        float  tthr = 0.f;
        if (lane < TT) {
            const float* tr = tgt + (size_t)(b*TT + lane)*5;
            const float wn = tr[2], hn = tr[3];
            const float cx = tr[0]*608.f, cy = tr[1]*608.f;
            const float gw = wn*608.f,    gh = hn*608.f;
            tvalid = (wn > 0.f);
            tbox = make_float4(cx - 0.5f*gw, cy - 0.5f*gh,
                               cx + 0.5f*gw, cy + 0.5f*gh);
            tthr = 0.25f*(gw*gh + 1e-9f);
        }
        const unsigned vmask = __ballot_sync(0xffffffffu, tvalid);
        const int nv = __popc(vmask);
        if (tvalid) {
            const int rank = __popc(vmask & ((1u << lane) - 1u));
            s_box[wid][rank] = tbox;
            s_thr[wid][rank] = tthr;
        } else if (lane < TT && lane >= nv) {
            s_box[wid][lane] = make_float4(1e30f, 1e30f, -1e30f, -1e30f);
            s_thr[wid][lane] = 1e30f;
        }

        const float rx[2] = {RX.x,RX.y};
        const float ry[2] = {RY.x,RY.y};
        const float rw[2] = {RW.x,RW.y};
        const float rh[2] = {RH.x,RH.y};
        const float rc[2] = {RC.x,RC.y};
        const float awh = 0.5f*c_aw[a], ahh = 0.5f*c_ah[a];

        float d1x[2], d2x[2], d1y[2], d2y[2], da4[2], spc[2];
        #pragma unroll
        for (int s = 0; s < PPT; s++) {
            const float sxv = fsigmoid(rx[s]);
            const float syv = fsigmoid(ry[s]);
            const float hw  = fexp(rw[s]) * awh;       // half-width
            const float hh  = fexp(rh[s]) * ahh;       // half-height
            const float dcx = (sxv + (float)(i0 + s)) * 8.f;
            const float dcy = (syv + (float)j) * 8.f;
            d1x[s] = dcx - hw;  d2x[s] = dcx + hw;
            d1y[s] = dcy - hh;  d2y[s] = dcy + hh;
            da4[s] = hw*hh;                            // da/4
            spc[s] = fsoftplus(rc[s]);                 // background conf term
        }
        __syncwarp();

        // hot loop: chunks of 5, inner fully unrolled (LDS batched per chunk);
        // sentinel slots contribute -1e30 and never affect the max
        float vm[2] = {-1e30f, -1e30f};                // max_t(0.75*inter - thr4)
        for (int t0 = 0; t0 < nv; t0 += 5) {
            #pragma unroll
            for (int u = 0; u < 5; u++) {
                const int t = t0 + u;                  // <= 19 always (nv <= 20)
                const float4 g    = s_box[wid][t];
                const float  thr4 = s_thr[wid][t];
                #pragma unroll
                for (int s = 0; s < PPT; s++) {
                    const float iw = fminf(d2x[s], g.z) - fmaxf(d1x[s], g.x);
                    const float ih = fminf(d2y[s], g.w) - fmaxf(d1y[s], g.y);
                    const float inter = fmaxf(iw, 0.f) * ih;   // single clamp
                    vm[s] = fmaxf(vm[s], fmaf(0.75f, inter, -thr4));
                }
            }
        }
        if (act) {
            #pragma unroll
            for (int s = 0; s < PPT; s++)
                if (!(vm[s] > da4[s])) accC += spc[s];   // bg conf (fore incl.)
        }

        // reduce conf only
        #pragma unroll
        for (int o = 16; o > 0; o >>= 1)
            accC += __shfl_down_sync(0xffffffffu, accC, o);
        if (lane == 0) sred[1][wid] = accC;
        __syncthreads();
        if (tid == 0) {
            double q1 = 0.0;
            #pragma unroll
            for (int k = 0; k < NW; k++) q1 += (double)sred[1][k];
            atomicAdd(&g_acc[1], q1);
        }
    } else {
        // ========== fore path: one warp per (batch, target) ==========
        const int T = (bx - GX)*NW + wid;     // 0..19
        Match m;
        bool okl = false; int flatl = -0x40000000;
        if (lane < TT) { m = match_slot(tgt, b, lane); okl = m.ok; flatl = m.flat; }

        if (T < TT) {
            const unsigned FULL = 0xffffffffu;
            const int myflat = __shfl_sync(FULL, flatl, T);
            const bool myok  = (__shfl_sync(FULL, (int)okl, T) != 0);
            const unsigned same = __ballot_sync(FULL, okl && (flatl == myflat));
            const bool win = myok && ((same >> (T+1)) == 0);   // last-wins dedup

            if (win) {
                const float tx = __shfl_sync(FULL, m.tx, T);
                const float ty = __shfl_sync(FULL, m.ty, T);
                const float tw = __shfl_sync(FULL, m.tw, T);
                const float th = __shfl_sync(FULL, m.th, T);
                const float w2 = __shfl_sync(FULL, m.sc, T);
                const int   cc = __shfl_sync(FULL, m.cls, T);

                const int fa    = myflat / HW;
                const int fcell = myflat - fa*HW;
                const int fj    = fcell / WW;
                const int fi    = fcell - fj*WW;
                const size_t so = ((size_t)(b*NAH + fa)*CH)*HW + (size_t)fcell;

                const float v5 = (lane < 5) ? x[so + (size_t)lane*HW] : 0.f;
                const float frx = __shfl_sync(FULL, v5, 0);
                const float fry = __shfl_sync(FULL, v5, 1);
                const float frw = __shfl_sync(FULL, v5, 2);
                const float frh = __shfl_sync(FULL, v5, 3);
                const float frc = __shfl_sync(FULL, v5, 4);

                // decode (IDENTICAL formulas to spatial path)
                const float fsx = fsigmoid(frx), fsy = fsigmoid(fry);
                const float fhw = fexp(frw) * (0.5f*c_aw[fa]);
                const float fhh = fexp(frh) * (0.5f*c_ah[fa]);
                const float fdcx = (fsx + (float)fi) * 8.f;
                const float fdcy = (fsy + (float)fj) * 8.f;
                const float fd1x = fdcx - fhw, fd2x = fdcx + fhw;
                const float fd1y = fdcy - fhh, fd2y = fdcy + fhh;
                const float fda4 = fhw*fhh;

                // recompute the EXACT spatial ignore decision (same single-clamp
                // formula; invalid slots give -1e30; fp max is order-independent)
                float v = -1e30f;
                if (lane < TT) {
                    const float iw = fminf(fd2x, m.g2x) - fmaxf(fd1x, m.g1x);
                    const float ih = fminf(fd2y, m.g2y) - fmaxf(fd1y, m.g1y);
                    const float inter = fmaxf(iw, 0.f) * ih;
                    v = fmaf(0.75f, inter, -m.thr4);
                }
                #pragma unroll
                for (int o = 16; o > 0; o >>= 1)
                    v = fmaxf(v, __shfl_xor_sync(FULL, v, o));
                const bool ign = (v > fda4);

                if (lane == 0) {
                    const float d0 = fsx - tx, d1 = fsy - ty;
                    const float d2 = frw - tw, d3 = frh - th;
                    accL += 0.5f*w2*(d0*d0 + d1*d1) + 0.5f*w2*(d2*d2 + d3*d3);
                    // fore conf, minus the bg term the spatial pass overcounted
                    accC += fsoftplus(-frc) - (ign ? 0.f : fsoftplus(frc));
                }
                // cooperative cls: sum_c softplus(rv) - rv_cc
                #pragma unroll
                for (int k = 0; k < 3; k++) {
                    const int c = lane + 32*k;
                    if (c < NC) {
                        const float rv = x[so + (size_t)(5+c)*HW];
                        accS += fsoftplus(rv);
                        if (c == cc) accS -= rv;
                    }
                }
            }
        }

        #pragma unroll
        for (int o = 16; o > 0; o >>= 1) {
            accL += __shfl_down_sync(0xffffffffu, accL, o);
            accC += __shfl_down_sync(0xffffffffu, accC, o);
            accS += __shfl_down_sync(0xffffffffu, accS, o);
        }
        if (lane == 0) { sred[0][wid] = accL; sred[1][wid] = accC; sred[2][wid] = accS; }
        __syncthreads();
        if (tid == 0) {
            double q0 = 0.0, q1 = 0.0, q2 = 0.0;
            #pragma unroll
            for (int k = 0; k < NW; k++) {
                q0 += (double)sred[0][k]; q1 += (double)sred[1][k]; q2 += (double)sred[2][k];
            }
            atomicAdd(&g_acc[0], q0);
            atomicAdd(&g_acc[1], q1);
            atomicAdd(&g_acc[2], q2);
        }
    }

    // ---- common finalize: ticket wraps to 0 each run ----
    if (tid == 0) {
        __threadfence();
        const unsigned old = atomicInc(&g_ticket, NBLK - 1);
        if (old == NBLK - 1) {
            #pragma unroll
            for (int k = 0; k < 3; k++) {
                unsigned long long raw = atomicExch((unsigned long long*)&g_acc[k], 0ull);
                out[k] = (float)(__longlong_as_double(raw) / (double)BB);
            }
        }
    }
}

extern "C" void kernel_launch(void* const* d_in, const int* in_sizes, int n_in,
                              void* d_out, int out_size) {
    const float* x = (const float*)d_in[0];
    const float* t = (const float*)d_in[1];
    float* out = (float*)d_out;
    dim3 grid(GX + FBX, BB);
    yolo_k<<<grid, BLK>>>(x, t, out);
}